// round 15
// baseline (speedup 1.0000x reference)
#include <cuda_runtime.h>

#define N_NODES 50000
#define N_EDGES 800000
#define HALF_E  (N_EDGES / 2)
#define IN_DIM  96
#define HID     32
#define OUT_DIM 64

#define PERSIST_BLOCKS 296   // 2 per SM (148 SMs)

// ---------------- scratch (no allocations allowed) ----------------
__device__ float g_y1 [N_NODES * HID];   // x @ W1l
__device__ float g_z1 [N_NODES * HID];   // x @ W1r + b1
__device__ float g_agg[N_NODES * HID];   // accumulator: layer1, then reused for layer2
__device__ float g_h  [N_NODES * HID];   // relu output of layer 1
__device__ float g_cnt[N_NODES];         // in-degree (float)
__device__ int2  g_epack[N_EDGES];       // packed (src, dst) int32
__device__ int   g_is64;                 // 1 if edge_index buffer is int64

// Vector reduction: 16B atomic add (sm_90+, PTX ISA 8.1).
__device__ __forceinline__ void red_add_v4(float* addr, float4 v) {
    asm volatile("red.global.add.v4.f32 [%0], {%1, %2, %3, %4};"
                 :: "l"(addr), "f"(v.x), "f"(v.y), "f"(v.z), "f"(v.w)
                 : "memory");
}

// ---------------- kernels ----------------

// Zero accumulator + counts (float4). Thread 0 of block 0 also sniffs the
// edge_index dtype: little-endian int64 with values in [0, 50000) has every
// odd 32-bit word == 0; for int32 data the probed words are random endpoints
// and P(all 16 zero) ~ (2e-5)^16 ~ 0. Probes spread across the buffer.
__global__ void k_init(const int* __restrict__ ei32) {
    int i = blockIdx.x * blockDim.x + threadIdx.x;
    if (i == 0) {
        int is64 = 1;
        #pragma unroll
        for (int k = 0; k < 16; k++) {
            int idx = 2 * (k * 49999) + 1;   // max 1,499,971 < 1.6M ints (both dtypes)
            if (ei32[idx] != 0) is64 = 0;
        }
        g_is64 = is64;
    }
    int stride = gridDim.x * blockDim.x;
    float4 z = make_float4(0.f, 0.f, 0.f, 0.f);
    for (int j = i; j < N_NODES * HID / 4; j += stride)
        ((float4*)g_agg)[j] = z;
    for (int j = i; j < N_NODES; j += stride)
        g_cnt[j] = 0.0f;
}

// Normalize edge index to packed int32 pairs; count in-degrees.
// Each thread handles 2 consecutive edges with vector loads (16B for the
// int64 path, 8B for int32): full sector utilization, MLP=2.
__global__ void k_edges(const int* __restrict__ ei32) {
    int e = 2 * (blockIdx.x * blockDim.x + threadIdx.x);
    if (e >= N_EDGES) return;    // N_EDGES even -> e+1 always valid when e valid
    int s0, d0, s1, d1;
    if (g_is64) {
        const longlong2* __restrict__ ei64 = (const longlong2*)ei32;
        longlong2 sp = __ldg(&ei64[e >> 1]);                 // src[e], src[e+1]
        longlong2 dp = __ldg(&ei64[(N_EDGES + e) >> 1]);     // dst[e], dst[e+1]
        s0 = (int)sp.x; s1 = (int)sp.y;
        d0 = (int)dp.x; d1 = (int)dp.y;
    } else {
        const int2* __restrict__ e2 = (const int2*)ei32;
        int2 sp = __ldg(&e2[e >> 1]);
        int2 dp = __ldg(&e2[(N_EDGES + e) >> 1]);
        s0 = sp.x; s1 = sp.y;
        d0 = dp.x; d1 = dp.y;
    }
    g_epack[e]     = make_int2(s0, d0);
    g_epack[e + 1] = make_int2(s1, d1);
    atomicAdd(&g_cnt[d0], 1.0f);
    atomicAdd(&g_cnt[d1], 1.0f);
}

// Fused: y1 = x @ W1l ; z1 = x @ W1r + b1.
// PERSISTENT: weights loaded into smem once per block; warp-per-row
// grid-stride loop; x broadcast lane->warp via shuffles (no smem staging).
__global__ __launch_bounds__(256) void k_lin1(const float* __restrict__ x,
                                              const float* __restrict__ W1l,
                                              const float* __restrict__ W1r,
                                              const float* __restrict__ b1) {
    __shared__ float sWl[IN_DIM * HID];
    __shared__ float sWr[IN_DIM * HID];

    int t = threadIdx.x;
    for (int i = t; i < IN_DIM * HID; i += 256) { sWl[i] = W1l[i]; sWr[i] = W1r[i]; }
    __syncthreads();

    int w    = t >> 5;
    int lane = t & 31;
    float bias = b1[lane];          // HID == 32, one bias per lane

    for (int row = blockIdx.x * 8 + w; row < N_NODES; row += gridDim.x * 8) {
        // Each lane holds 3 x values (96 = 3*32), broadcast via shuffle.
        const float* xr = x + row * IN_DIM;
        float x0 = xr[lane];
        float x1 = xr[lane + 32];
        float x2 = xr[lane + 64];

        float a1 = 0.0f;
        float a2 = bias;
        #pragma unroll
        for (int k = 0; k < 32; k++) {
            float xv = __shfl_sync(0xffffffffu, x0, k);
            a1 = fmaf(xv, sWl[k * HID + lane], a1);
            a2 = fmaf(xv, sWr[k * HID + lane], a2);
        }
        #pragma unroll
        for (int k = 0; k < 32; k++) {
            float xv = __shfl_sync(0xffffffffu, x1, k);
            a1 = fmaf(xv, sWl[(k + 32) * HID + lane], a1);
            a2 = fmaf(xv, sWr[(k + 32) * HID + lane], a2);
        }
        #pragma unroll
        for (int k = 0; k < 32; k++) {
            float xv = __shfl_sync(0xffffffffu, x2, k);
            a1 = fmaf(xv, sWl[(k + 64) * HID + lane], a1);
            a2 = fmaf(xv, sWr[(k + 64) * HID + lane], a2);
        }
        g_y1[row * HID + lane] = a1;
        g_z1[row * HID + lane] = a2;
    }
}

// Scatter-add, MLP=2: each thread handles TWO independent edges (e and
// e+HALF_E), front-batching both index loads and both feature gathers
// before issuing the two vector-atomic reductions. 8 lanes per edge,
// each lane moves one float4. LAYER=0: src g_y1, LAYER=1: src g_h.
template <int LAYER>
__global__ __launch_bounds__(256) void k_scatter() {
    int gtid = blockIdx.x * blockDim.x + threadIdx.x;
    int e    = gtid >> 3;          // first edge index (0 .. HALF_E-1)
    int sub  = gtid & 7;           // float4 chunk 0..7 (8*4 = 32 = HID)
    if (e >= HALF_E) return;
    const int2* __restrict__ ep = g_epack;
    const float4* __restrict__ src =
        (const float4*)((LAYER == 0) ? g_y1 : g_h);

    // Front-batch: both index loads, then both gathers (independent chains).
    int2 sd0 = __ldg(&ep[e]);
    int2 sd1 = __ldg(&ep[e + HALF_E]);
    float4 v0 = __ldg(&src[sd0.x * (HID / 4) + sub]);
    float4 v1 = __ldg(&src[sd1.x * (HID / 4) + sub]);

    red_add_v4(g_agg + sd0.y * HID + sub * 4, v0);
    red_add_v4(g_agg + sd1.y * HID + sub * 4, v1);
}

// h = relu(agg/max(cnt,1) + z1); re-zero agg for layer 2 in the same pass.
__global__ void k_relu() {
    int i = blockIdx.x * blockDim.x + threadIdx.x;  // float4 index
    if (i >= N_NODES * HID / 4) return;
    float c   = g_cnt[i >> 3];                       // 8 float4 per row
    float inv = 1.0f / fmaxf(c, 1.0f);
    float4 a  = ((float4*)g_agg)[i];
    float4 z  = ((float4*)g_z1)[i];
    float4 h;
    h.x = fmaxf(fmaf(a.x, inv, z.x), 0.0f);
    h.y = fmaxf(fmaf(a.y, inv, z.y), 0.0f);
    h.z = fmaxf(fmaf(a.z, inv, z.z), 0.0f);
    h.w = fmaxf(fmaf(a.w, inv, z.w), 0.0f);
    ((float4*)g_h)[i] = h;
    ((float4*)g_agg)[i] = make_float4(0.f, 0.f, 0.f, 0.f);
}

// out = (agg2/max(cnt,1)) @ W2l + h @ W2r + b2.
// PERSISTENT: weights in smem once per block; warp-per-row grid-stride;
// each lane produces output columns lane and lane+32; row data via shuffle.
__global__ __launch_bounds__(256) void k_out(const float* __restrict__ W2l,
                                             const float* __restrict__ W2r,
                                             const float* __restrict__ b2,
                                             float* __restrict__ out) {
    __shared__ float sWl[HID * OUT_DIM];
    __shared__ float sWr[HID * OUT_DIM];

    int t = threadIdx.x;
    for (int i = t; i < HID * OUT_DIM; i += 256) { sWl[i] = W2l[i]; sWr[i] = W2r[i]; }
    __syncthreads();

    int w    = t >> 5;
    int lane = t & 31;
    float b_lo = b2[lane];
    float b_hi = b2[lane + 32];

    for (int row = blockIdx.x * 8 + w; row < N_NODES; row += gridDim.x * 8) {
        float inv = 1.0f / fmaxf(g_cnt[row], 1.0f);     // broadcast load
        float av  = g_agg[row * HID + lane] * inv;       // pre-scale: all lanes same row
        float hv  = g_h  [row * HID + lane];

        float acc0 = b_lo;
        float acc1 = b_hi;
        #pragma unroll
        for (int k = 0; k < 32; k++) {
            float a = __shfl_sync(0xffffffffu, av, k);
            float h = __shfl_sync(0xffffffffu, hv, k);
            acc0 = fmaf(a, sWl[k * OUT_DIM + lane],      acc0);
            acc0 = fmaf(h, sWr[k * OUT_DIM + lane],      acc0);
            acc1 = fmaf(a, sWl[k * OUT_DIM + lane + 32], acc1);
            acc1 = fmaf(h, sWr[k * OUT_DIM + lane + 32], acc1);
        }
        out[row * OUT_DIM + lane]      = acc0;
        out[row * OUT_DIM + lane + 32] = acc1;
    }
}

// ---------------- launch ----------------
extern "C" void kernel_launch(void* const* d_in, const int* in_sizes, int n_in,
                              void* d_out, int out_size) {
    const float* x   = (const float*)d_in[0];
    const int*   ei  = (const int*)d_in[1];     // int32 view; dtype sniffed on device
    const float* W1l = (const float*)d_in[2];
    const float* W1r = (const float*)d_in[3];
    const float* b1  = (const float*)d_in[4];
    const float* W2l = (const float*)d_in[5];
    const float* W2r = (const float*)d_in[6];
    const float* b2  = (const float*)d_in[7];
    float*       out = (float*)d_out;

    k_init  <<<1024, 256>>>(ei);
    k_edges <<<(N_EDGES / 2 + 255) / 256, 256>>>(ei);
    k_lin1  <<<PERSIST_BLOCKS, 256>>>(x, W1l, W1r, b1);
    k_scatter<0><<<(HALF_E * 8 + 255) / 256, 256>>>();
    k_relu  <<<(N_NODES * HID / 4 + 255) / 256, 256>>>();
    k_scatter<1><<<(HALF_E * 8 + 255) / 256, 256>>>();
    k_out   <<<PERSIST_BLOCKS, 256>>>(W2l, W2r, b2, out);
}